// round 11
// baseline (speedup 1.0000x reference)
#include <cuda_runtime.h>
#include <cuda_fp16.h>
#include <cstdint>
#include <math.h>

// Qwen3.5 TopK Router — 3-pass FP16-split mma.sync(m16n8k16) + ldmatrix.
// Warp tile 64x32 (fragment traffic per MAC x0.75 -> smem crossbar no longer
// binds), BM=64, 4 warps/CTA, 4 CTAs/SM, grid=256.
// x' = x*1024, w' = w*64; hi = f16_rn(v), lo = f16_rn(v-hi);
// acc += Ah*Bh + Al*Bh + Ah*Bl; logits = acc/65536. Residual ~2^-22.
//
// Output (float32): [T*E logits][T*K weights][T*K indices-as-float]

#define D_DIM  2048
#define E_EXP  128
#define TOPK   8
#define BM     64                 // tokens per CTA
#define KC     32                 // fp32 K per chunk
#define NCH    (D_DIM / KC)       // 64
#define NT     128
#define LPAD   129

#define SX      1024.0f
#define SW      64.0f
#define RESCALE (1.0f / 65536.0f)

// stage (64B rows, granule swizzle g ^ ((r>>1)&3)):
//   Ah 4K | Al 4K | Bh 8K | Bl 8K = 24KB; 2 stages
#define OFF_AH   0
#define OFF_AL   4096
#define OFF_BH   8192
#define OFF_BL   16384
#define STAGE_B  24576
#define SMEM_B   49152            // 2 stages; epilogue 64*129*4 = 33024 alias

#define MMA_F16(d, a0, a1, a2, a3, b0, b1)                                    \
    asm volatile(                                                             \
        "mma.sync.aligned.m16n8k16.row.col.f32.f16.f16.f32 "                  \
        "{%0,%1,%2,%3}, {%4,%5,%6,%7}, {%8,%9}, {%0,%1,%2,%3};"               \
        : "+f"((d)[0]), "+f"((d)[1]), "+f"((d)[2]), "+f"((d)[3])              \
        : "r"(a0), "r"(a1), "r"(a2), "r"(a3), "r"(b0), "r"(b1))

#define LDSM_X4(r, addr)                                                      \
    asm volatile(                                                             \
        "ldmatrix.sync.aligned.m8n8.x4.shared.b16 {%0,%1,%2,%3}, [%4];"       \
        : "=r"((r)[0]), "=r"((r)[1]), "=r"((r)[2]), "=r"((r)[3])              \
        : "r"(addr))

static __device__ __forceinline__ uint32_t smem_u32(const void* p) {
    uint32_t a;
    asm("{ .reg .u64 t; cvta.to.shared.u64 t, %1; cvt.u32.u64 %0, t; }"
        : "=r"(a) : "l"(p));
    return a;
}
static __device__ __forceinline__ void split2(float x0, float x1,
                                              uint32_t& hi, uint32_t& lo) {
    half2 h = __floats2half2_rn(x0, x1);
    float2 hf = __half22float2(h);
    half2 l = __floats2half2_rn(x0 - hf.x, x1 - hf.y);
    hi = *(uint32_t*)&h;
    lo = *(uint32_t*)&l;
}
static __device__ __forceinline__ void split4(float4 v, float s,
                                              uint2& hi, uint2& lo) {
    uint32_t h0, l0, h1, l1;
    split2(v.x * s, v.y * s, h0, l0);
    split2(v.z * s, v.w * s, h1, l1);
    hi = make_uint2(h0, h1);
    lo = make_uint2(l0, l1);
}

__global__ __launch_bounds__(NT, 4)
void router_mma(const float* __restrict__ X,
                const float* __restrict__ W,
                float* __restrict__ out, int T)
{
    extern __shared__ __align__(16) uint32_t smem[];
    __shared__ float smax[BM];
    __shared__ float srsum[BM];

    const uint32_t sbase = smem_u32(smem);
    const int tid  = threadIdx.x;
    const int wid  = tid >> 5;          // 0..3
    const int lane = tid & 31;
    const int row0 = blockIdx.x * BM;

    // -------- producer mapping (64B rows, swizzle g ^ ((r>>1)&3)) --------
    const int psub = lane >> 3;                  // 0..3
    const int pcol = (lane & 7) * 4;             // fp32 col
    const int pg   = (lane & 7) >> 1;            // 16B granule
    const int psb  = (lane & 1) * 8;
    // A: 64 rows; warp w rows 16w+4q+psub, q=0..3
    const int rA0 = 16 * wid + psub;
    const float* gA0 = X + (size_t)(row0 + rA0) * D_DIM + pcol;
    const uint32_t soffA0 = (uint32_t)(rA0 * 64
                          + ((pg ^ ((rA0 >> 1) & 3)) << 4) + psb);
    // B: 128 rows; warp w rows 32w+4q+psub, q=0..7
    const int rB0 = 32 * wid + psub;
    const float* gB0 = W + (size_t)rB0 * D_DIM + pcol;
    const uint32_t soffB0 = (uint32_t)(rB0 * 64
                          + ((pg ^ ((rB0 >> 1) & 3)) << 4) + psb);

    // -------- consumer mapping: 4 warps, tile 64(M) x 32(N) --------
    const int g_  = lane >> 2;
    const int tg  = lane & 3;
    const int ncol0 = wid * 32;
    const int kbo   = wid & 1;

    // ldmatrix base offsets (mt=0 / p=0, kb=0); +1024*mt|p ; ^32 for kb=1
    uint32_t offA0, offB0;
    {
        const int rA  = (lane & 7) + ((lane >> 3) & 1) * 8;
        const int gsA = lane >> 4;
        offA0 = (uint32_t)(rA * 64 + ((gsA ^ ((rA >> 1) & 3)) << 4));
        const int rB  = (lane & 7) + ((lane >> 4) << 3);
        const int gsB = (lane >> 3) & 1;
        const int rowB = ncol0 + rB;
        offB0 = (uint32_t)(rowB * 64 + ((gsB ^ ((rowB >> 1) & 3)) << 4));
    }

    float acc[4][4][4];
    #pragma unroll
    for (int mt = 0; mt < 4; mt++)
        #pragma unroll
        for (int nt = 0; nt < 4; nt++)
            #pragma unroll
            for (int i = 0; i < 4; i++) acc[mt][nt][i] = 0.0f;

    float4 ra[4];

    // ---- prologue: chunk 0 -> stage 0 ----
    {
        char* st = (char*)smem;
        #pragma unroll
        for (int q = 0; q < 4; q++) {
            float4 v = *(const float4*)(gA0 + (size_t)q * 4 * D_DIM);
            const uint32_t so = (soffA0 + q * 256u) ^ ((uint32_t)(q & 1) << 5);
            uint2 hi, lo;
            split4(v, SX, hi, lo);
            *(uint2*)(st + OFF_AH + so) = hi;
            *(uint2*)(st + OFF_AL + so) = lo;
        }
        #pragma unroll
        for (int q = 0; q < 8; q++) {
            float4 v = *(const float4*)(gB0 + (size_t)q * 4 * D_DIM);
            const uint32_t so = (soffB0 + q * 256u) ^ ((uint32_t)(q & 1) << 5);
            uint2 hi, lo;
            split4(v, SW, hi, lo);
            *(uint2*)(st + OFF_BH + so) = hi;
            *(uint2*)(st + OFF_BL + so) = lo;
        }
    }
    __syncthreads();

    // ---- main loop ----
    for (int c = 0; c < NCH; ++c) {
        // prefetch A(c+1) into registers (DRAM latency over compute)
        if (c + 1 < NCH) {
            const int ko = (c + 1) * KC;
            #pragma unroll
            for (int q = 0; q < 4; q++)
                ra[q] = *(const float4*)(gA0 + (size_t)q * 4 * D_DIM + ko);
        }

        const uint32_t stg = sbase + (uint32_t)(c & 1) * STAGE_B;

        #pragma unroll
        for (int kbi = 0; kbi < 2; kbi++) {
            const int kb = kbi ^ kbo;
            const uint32_t kx = (uint32_t)kb << 5;

            uint32_t bh[2][4], bl[2][4];
            #pragma unroll
            for (int p = 0; p < 2; p++) {
                LDSM_X4(bh[p], stg + OFF_BH + ((offB0 + p * 1024u) ^ kx));
                LDSM_X4(bl[p], stg + OFF_BL + ((offB0 + p * 1024u) ^ kx));
            }

            #pragma unroll
            for (int mt = 0; mt < 4; mt++) {
                uint32_t ah[4], al[4];
                const uint32_t ao = (offA0 + mt * 1024u) ^ kx;
                LDSM_X4(ah, stg + OFF_AH + ao);
                LDSM_X4(al, stg + OFF_AL + ao);

                #pragma unroll
                for (int nt = 0; nt < 4; nt++) {
                    const int p = nt >> 1, h = (nt & 1) * 2;
                    MMA_F16(acc[mt][nt], ah[0], ah[1], ah[2], ah[3],
                            bh[p][h], bh[p][h + 1]);
                }
                #pragma unroll
                for (int nt = 0; nt < 4; nt++) {
                    const int p = nt >> 1, h = (nt & 1) * 2;
                    MMA_F16(acc[mt][nt], al[0], al[1], al[2], al[3],
                            bh[p][h], bh[p][h + 1]);
                }
                #pragma unroll
                for (int nt = 0; nt < 4; nt++) {
                    const int p = nt >> 1, h = (nt & 1) * 2;
                    MMA_F16(acc[mt][nt], ah[0], ah[1], ah[2], ah[3],
                            bl[p][h], bl[p][h + 1]);
                }
            }
        }

        // tail: commit A(c+1); load+split B(c+1) straight from L2-resident W
        if (c + 1 < NCH) {
            char* stn = (char*)smem + ((c + 1) & 1) * STAGE_B;
            #pragma unroll
            for (int q = 0; q < 4; q++) {
                const uint32_t so = (soffA0 + q * 256u) ^ ((uint32_t)(q & 1) << 5);
                uint2 hi, lo;
                split4(ra[q], SX, hi, lo);
                *(uint2*)(stn + OFF_AH + so) = hi;
                *(uint2*)(stn + OFF_AL + so) = lo;
            }
            const int ko = (c + 1) * KC;
            #pragma unroll
            for (int q = 0; q < 8; q++) {
                float4 v = *(const float4*)(gB0 + (size_t)q * 4 * D_DIM + ko);
                const uint32_t so = (soffB0 + q * 256u) ^ ((uint32_t)(q & 1) << 5);
                uint2 hi, lo;
                split4(v, SW, hi, lo);
                *(uint2*)(stn + OFF_BH + so) = hi;
                *(uint2*)(stn + OFF_BL + so) = lo;
            }
        }
        __syncthreads();
    }

    // ---- epilogue: rescale accum -> smem logits tile ----
    float* Ls = (float*)smem;   // [BM][LPAD] = 33024 B
    #pragma unroll
    for (int mt = 0; mt < 4; mt++) {
        #pragma unroll
        for (int nt = 0; nt < 4; nt++) {
            const int r_ = mt * 16 + g_;
            const int c_ = ncol0 + nt * 8 + tg * 2;
            Ls[r_ * LPAD + c_]           = acc[mt][nt][0] * RESCALE;
            Ls[r_ * LPAD + c_ + 1]       = acc[mt][nt][1] * RESCALE;
            Ls[(r_ + 8) * LPAD + c_]     = acc[mt][nt][2] * RESCALE;
            Ls[(r_ + 8) * LPAD + c_ + 1] = acc[mt][nt][3] * RESCALE;
        }
    }
    __syncthreads();

    // per-token max & exp-sum
    if (tid < BM) {
        const float* r = Ls + tid * LPAD;
        float m = r[0];
        #pragma unroll 4
        for (int e = 1; e < E_EXP; e++) m = fmaxf(m, r[e]);
        float s = 0.0f;
        #pragma unroll 4
        for (int e = 0; e < E_EXP; e++) s += __expf(r[e] - m);
        smax[tid]  = m;
        srsum[tid] = 1.0f / s;
    }
    __syncthreads();

    // softmax probs -> smem overwrite + coalesced logits write
    for (int i = tid; i < BM * E_EXP; i += NT) {
        const int t = i >> 7;
        const int e = i & 127;
        const float p = __expf(Ls[t * LPAD + e] - smax[t]) * srsum[t];
        Ls[t * LPAD + e] = p;
        out[(size_t)(row0 + t) * E_EXP + e] = p;
    }
    __syncthreads();

    // top-8 (strict > keeps lowest index on ties) + renormalize
    if (tid < BM) {
        float* r = Ls + tid * LPAD;
        float vals[TOPK];
        int   idxs[TOPK];
        float s = 0.0f;
        #pragma unroll
        for (int k = 0; k < TOPK; k++) {
            float bv = -1.0f;
            int   bi = 0;
            for (int e = 0; e < E_EXP; e++) {
                float v = r[e];
                if (v > bv) { bv = v; bi = e; }
            }
            r[bi]   = -1.0f;
            vals[k] = bv;
            idxs[k] = bi;
            s += bv;
        }
        const float rs = 1.0f / s;
        const size_t bw = (size_t)T * E_EXP + (size_t)(row0 + tid) * TOPK;
        const size_t bx = (size_t)T * E_EXP + (size_t)T * TOPK + (size_t)(row0 + tid) * TOPK;
        #pragma unroll
        for (int k = 0; k < TOPK; k++) {
            out[bw + k] = vals[k] * rs;
            out[bx + k] = (float)idxs[k];
        }
    }
}

extern "C" void kernel_launch(void* const* d_in, const int* in_sizes, int n_in,
                              void* d_out, int out_size)
{
    const float* X = (const float*)d_in[0];   // hidden_states [T, 2048]
    const float* W = (const float*)d_in[1];   // weight        [128, 2048]
    float* out = (float*)d_out;

    const int T = in_sizes[0] / D_DIM;        // 16384
    static int configured = -1;
    if (configured < 0) {
        cudaFuncSetAttribute(router_mma,
                             cudaFuncAttributeMaxDynamicSharedMemorySize, SMEM_B);
        configured = 1;
    }
    router_mma<<<T / BM, NT, SMEM_B>>>(X, W, out, T);
}

// round 12
// speedup vs baseline: 1.3077x; 1.3077x over previous
#include <cuda_runtime.h>
#include <cuda_fp16.h>
#include <cstdint>
#include <math.h>

// Qwen3.5 TopK Router — 3-pass FP16-split mma.sync(m16n8k16) + ldmatrix.
// Round-10 GEMM (bit-identical) + producer hidden mid-chunk + redux-based
// warp-parallel fused softmax/top-8 epilogue.
// x' = x*1024, w' = w*64; hi = f16_rn(v), lo = f16_rn(v-hi);
// acc += Ah*Bh + Al*Bh + Ah*Bl; logits = acc/65536. Residual ~2^-22.
//
// Output (float32): [T*E logits][T*K weights][T*K indices-as-float]

#define D_DIM  2048
#define E_EXP  128
#define TOPK   8
#define BM     128
#define KC     32
#define NCH    (D_DIM / KC)       // 64
#define NT     512
#define LPAD   129

#define SX      1024.0f
#define SW      64.0f
#define RESCALE (1.0f / 65536.0f)

#define OFF_AH   0
#define OFF_AL   8192
#define OFF_BH   16384
#define OFF_BL   24576
#define STAGE_B  32768
#define SMEM_B   66560

#define MMA_F16(d, a0, a1, a2, a3, b0, b1)                                    \
    asm volatile(                                                             \
        "mma.sync.aligned.m16n8k16.row.col.f32.f16.f16.f32 "                  \
        "{%0,%1,%2,%3}, {%4,%5,%6,%7}, {%8,%9}, {%0,%1,%2,%3};"               \
        : "+f"((d)[0]), "+f"((d)[1]), "+f"((d)[2]), "+f"((d)[3])              \
        : "r"(a0), "r"(a1), "r"(a2), "r"(a3), "r"(b0), "r"(b1))

#define LDSM_X4(r, addr)                                                      \
    asm volatile(                                                             \
        "ldmatrix.sync.aligned.m8n8.x4.shared.b16 {%0,%1,%2,%3}, [%4];"       \
        : "=r"((r)[0]), "=r"((r)[1]), "=r"((r)[2]), "=r"((r)[3])              \
        : "r"(addr))

static __device__ __forceinline__ uint32_t smem_u32(const void* p) {
    uint32_t a;
    asm("{ .reg .u64 t; cvta.to.shared.u64 t, %1; cvt.u32.u64 %0, t; }"
        : "=r"(a) : "l"(p));
    return a;
}
static __device__ __forceinline__ void split2(float x0, float x1,
                                              uint32_t& hi, uint32_t& lo) {
    half2 h = __floats2half2_rn(x0, x1);
    float2 hf = __half22float2(h);
    half2 l = __floats2half2_rn(x0 - hf.x, x1 - hf.y);
    hi = *(uint32_t*)&h;
    lo = *(uint32_t*)&l;
}
static __device__ __forceinline__ void split4(float4 v, float s,
                                              uint2& hi, uint2& lo) {
    uint32_t h0, l0, h1, l1;
    split2(v.x * s, v.y * s, h0, l0);
    split2(v.z * s, v.w * s, h1, l1);
    hi = make_uint2(h0, h1);
    lo = make_uint2(l0, l1);
}
// orderable-uint transform for float max over possibly-negative values
static __device__ __forceinline__ uint32_t ford(float f) {
    uint32_t b = __float_as_uint(f);
    return b ^ (uint32_t)(((int32_t)b >> 31) | 0x80000000);
}
static __device__ __forceinline__ float finv(uint32_t u) {
    uint32_t m = (uint32_t)(((int32_t)(~u) >> 31) | 0x80000000);
    return __uint_as_float(u ^ m);
}

__global__ __launch_bounds__(NT, 1)
void router_mma(const float* __restrict__ X,
                const float* __restrict__ W,
                float* __restrict__ out, int T)
{
    extern __shared__ __align__(16) uint32_t smem[];

    const uint32_t sbase = smem_u32(smem);
    const int tid  = threadIdx.x;
    const int wid  = tid >> 5;
    const int lane = tid & 31;
    const int row0 = blockIdx.x * BM;

    // -------- producer mapping (64B rows, swizzle g ^ ((r>>1)&3)) --------
    const int psub = lane >> 3;
    const int pcol = (lane & 7) * 4;
    const int pg   = (lane & 7) >> 1;
    const int psb  = (lane & 1) * 8;
    const float* gA[2];
    const float* gB[2];
    uint32_t soff[2];
    #pragma unroll
    for (int q = 0; q < 2; q++) {
        const int r = 8 * wid + 4 * q + psub;
        gA[q] = X + (size_t)(row0 + r) * D_DIM + pcol;
        gB[q] = W + (size_t)r * D_DIM + pcol;
        soff[q] = (uint32_t)(r * 64 + ((pg ^ ((r >> 1) & 3)) << 4) + psb);
    }

    // -------- consumer mapping: warp grid 4(M) x 4(N), tile 32x32 --------
    const int g_  = lane >> 2;
    const int tg  = lane & 3;
    const int mrow0 = (wid & 3) * 32;
    const int ncol0 = (wid >> 2) * 32;
    const int kbo   = wid & 1;

    uint32_t offA[2][2], offB[2][2];
    {
        const int rA  = (lane & 7) + ((lane >> 3) & 1) * 8;
        const int gsA = lane >> 4;
        #pragma unroll
        for (int mt = 0; mt < 2; mt++) {
            const int row = mrow0 + mt * 16 + rA;
            const int sw  = (row >> 1) & 3;
            #pragma unroll
            for (int kb = 0; kb < 2; kb++)
                offA[mt][kb] = (uint32_t)(row * 64 + (((kb * 2 + gsA) ^ sw) << 4));
        }
        const int rB  = (lane & 7) + ((lane >> 4) << 3);
        const int gsB = (lane >> 3) & 1;
        #pragma unroll
        for (int p = 0; p < 2; p++) {
            const int row = ncol0 + p * 16 + rB;
            const int sw  = (row >> 1) & 3;
            #pragma unroll
            for (int kb = 0; kb < 2; kb++)
                offB[p][kb] = (uint32_t)(row * 64 + (((kb * 2 + gsB) ^ sw) << 4));
        }
    }

    float acc[2][4][4];
    #pragma unroll
    for (int mt = 0; mt < 2; mt++)
        #pragma unroll
        for (int nt = 0; nt < 4; nt++)
            #pragma unroll
            for (int i = 0; i < 4; i++) acc[mt][nt][i] = 0.0f;

    float4 ra[2], rb[2];

    // ---- prologue: chunk 0 -> stage 0 ----
    #pragma unroll
    for (int q = 0; q < 2; q++) {
        ra[q] = *(const float4*)gA[q];
        rb[q] = *(const float4*)gB[q];
    }
    {
        char* st = (char*)smem;
        #pragma unroll
        for (int q = 0; q < 2; q++) {
            uint2 hi, lo;
            split4(ra[q], SX, hi, lo);
            *(uint2*)(st + OFF_AH + soff[q]) = hi;
            *(uint2*)(st + OFF_AL + soff[q]) = lo;
            split4(rb[q], SW, hi, lo);
            *(uint2*)(st + OFF_BH + soff[q]) = hi;
            *(uint2*)(st + OFF_BL + soff[q]) = lo;
        }
    }
    __syncthreads();

    // one kb block: JIT loads + 3 MMA passes (order as round 10)
    #define KB_BLOCK(KB)                                                      \
    {                                                                         \
        const int kb = (KB);                                                  \
        uint32_t ah[2][4], al[2][4], bh[2][4], bl[2][4];                      \
        _Pragma("unroll")                                                     \
        for (int mt = 0; mt < 2; mt++)                                        \
            LDSM_X4(ah[mt], stg + OFF_AH + offA[mt][kb]);                     \
        _Pragma("unroll")                                                     \
        for (int p = 0; p < 2; p++)                                           \
            LDSM_X4(bh[p], stg + OFF_BH + offB[p][kb]);                       \
        _Pragma("unroll")                                                     \
        for (int mt = 0; mt < 2; mt++)                                        \
            _Pragma("unroll")                                                 \
            for (int nt = 0; nt < 4; nt++) {                                  \
                const int p = nt >> 1, h = (nt & 1) * 2;                      \
                MMA_F16(acc[mt][nt], ah[mt][0], ah[mt][1], ah[mt][2],         \
                        ah[mt][3], bh[p][h], bh[p][h + 1]);                   \
            }                                                                 \
        _Pragma("unroll")                                                     \
        for (int mt = 0; mt < 2; mt++)                                        \
            LDSM_X4(al[mt], stg + OFF_AL + offA[mt][kb]);                     \
        _Pragma("unroll")                                                     \
        for (int mt = 0; mt < 2; mt++)                                        \
            _Pragma("unroll")                                                 \
            for (int nt = 0; nt < 4; nt++) {                                  \
                const int p = nt >> 1, h = (nt & 1) * 2;                      \
                MMA_F16(acc[mt][nt], al[mt][0], al[mt][1], al[mt][2],         \
                        al[mt][3], bh[p][h], bh[p][h + 1]);                   \
            }                                                                 \
        _Pragma("unroll")                                                     \
        for (int p = 0; p < 2; p++)                                           \
            LDSM_X4(bl[p], stg + OFF_BL + offB[p][kb]);                       \
        _Pragma("unroll")                                                     \
        for (int mt = 0; mt < 2; mt++)                                        \
            _Pragma("unroll")                                                 \
            for (int nt = 0; nt < 4; nt++) {                                  \
                const int p = nt >> 1, h = (nt & 1) * 2;                      \
                MMA_F16(acc[mt][nt], ah[mt][0], ah[mt][1], ah[mt][2],         \
                        ah[mt][3], bl[p][h], bl[p][h + 1]);                   \
            }                                                                 \
    }

    // ---- main loop ----
    for (int c = 0; c < NCH; ++c) {
        if (c + 1 < NCH) {
            const int ko = (c + 1) * KC;
            #pragma unroll
            for (int q = 0; q < 2; q++) {
                ra[q] = *(const float4*)(gA[q] + ko);
                rb[q] = *(const float4*)(gB[q] + ko);
            }
        }

        const uint32_t stg = sbase + (uint32_t)(c & 1) * STAGE_B;

        KB_BLOCK(kbo)

        // producer hidden in the shadow of the second kb block's MMAs
        if (c + 1 < NCH) {
            char* stn = (char*)smem + ((c + 1) & 1) * STAGE_B;
            #pragma unroll
            for (int q = 0; q < 2; q++) {
                uint2 hi, lo;
                split4(ra[q], SX, hi, lo);
                *(uint2*)(stn + OFF_AH + soff[q]) = hi;
                *(uint2*)(stn + OFF_AL + soff[q]) = lo;
                split4(rb[q], SW, hi, lo);
                *(uint2*)(stn + OFF_BH + soff[q]) = hi;
                *(uint2*)(stn + OFF_BL + soff[q]) = lo;
            }
        }

        KB_BLOCK(kbo ^ 1)

        __syncthreads();
    }

    // ---- epilogue: rescale accum -> smem logits tile ----
    float* Ls = (float*)smem;   // [BM][LPAD]
    #pragma unroll
    for (int mt = 0; mt < 2; mt++) {
        #pragma unroll
        for (int nt = 0; nt < 4; nt++) {
            const int r_ = mrow0 + mt * 16 + g_;
            const int c_ = ncol0 + nt * 8 + tg * 2;
            Ls[r_ * LPAD + c_]           = acc[mt][nt][0] * RESCALE;
            Ls[r_ * LPAD + c_ + 1]       = acc[mt][nt][1] * RESCALE;
            Ls[(r_ + 8) * LPAD + c_]     = acc[mt][nt][2] * RESCALE;
            Ls[(r_ + 8) * LPAD + c_ + 1] = acc[mt][nt][3] * RESCALE;
        }
    }
    __syncthreads();

    // ---- warp-parallel softmax + top-8: warp w -> tokens 8w..8w+7 ----
    const size_t wbase = (size_t)T * E_EXP;
    const size_t xbase = wbase + (size_t)T * TOPK;
    #pragma unroll 1
    for (int j = 0; j < 8; j++) {
        const int t = wid * 8 + j;
        const float* lr = Ls + t * LPAD + lane;
        float v0 = lr[0], v1 = lr[32], v2 = lr[64], v3 = lr[96];

        // warp max (redux on ordered uints)
        float mx = fmaxf(fmaxf(v0, v1), fmaxf(v2, v3));
        mx = finv(__reduce_max_sync(0xFFFFFFFFu, ford(mx)));

        float e0 = __expf(v0 - mx), e1 = __expf(v1 - mx);
        float e2 = __expf(v2 - mx), e3 = __expf(v3 - mx);
        float s = (e0 + e1) + (e2 + e3);
        #pragma unroll
        for (int o = 16; o > 0; o >>= 1) s += __shfl_xor_sync(0xFFFFFFFFu, s, o);
        const float rs = 1.0f / s;

        // probabilities (coalesced 128B stores per group)
        float* po = out + (size_t)(row0 + t) * E_EXP + lane;
        po[0]  = e0 * rs;
        po[32] = e1 * rs;
        po[64] = e2 * rs;
        po[96] = e3 * rs;

        // top-8 on e (positive floats order as uints); lowest index on ties
        float wv = 0.0f; int wi = 0; float s8 = 0.0f;
        #pragma unroll
        for (int k = 0; k < TOPK; k++) {
            float bv = e0; int bq = 0;
            if (e1 > bv) { bv = e1; bq = 1; }
            if (e2 > bv) { bv = e2; bq = 2; }
            if (e3 > bv) { bv = e3; bq = 3; }
            const uint32_t kbits = __float_as_uint(bv);
            const uint32_t wk = __reduce_max_sync(0xFFFFFFFFu, kbits);
            uint32_t cand = (kbits == wk) ? (uint32_t)(lane + 32 * bq)
                                          : 0xFFFFFFFFu;
            const uint32_t idx = __reduce_min_sync(0xFFFFFFFFu, cand);
            const float bval = __uint_as_float(wk);
            s8 += bval;
            if (lane == k) { wv = bval; wi = (int)idx; }
            if ((int)(idx & 31u) == lane) {
                const int q = (int)(idx >> 5);
                e0 = (q == 0) ? -1.0f : e0;
                e1 = (q == 1) ? -1.0f : e1;
                e2 = (q == 2) ? -1.0f : e2;
                e3 = (q == 3) ? -1.0f : e3;
            }
        }
        if (lane < TOPK) {
            const float rs8 = 1.0f / s8;
            out[wbase + (size_t)(row0 + t) * TOPK + lane] = wv * rs8;
            out[xbase + (size_t)(row0 + t) * TOPK + lane] = (float)wi;
        }
    }
}

extern "C" void kernel_launch(void* const* d_in, const int* in_sizes, int n_in,
                              void* d_out, int out_size)
{
    const float* X = (const float*)d_in[0];   // hidden_states [T, 2048]
    const float* W = (const float*)d_in[1];   // weight        [128, 2048]
    float* out = (float*)d_out;

    const int T = in_sizes[0] / D_DIM;        // 16384
    static int configured = -1;
    if (configured < 0) {
        cudaFuncSetAttribute(router_mma,
                             cudaFuncAttributeMaxDynamicSharedMemorySize, SMEM_B);
        configured = 1;
    }
    router_mma<<<T / BM, NT, SMEM_B>>>(X, W, out, T);
}

// round 13
// speedup vs baseline: 1.4197x; 1.0857x over previous
#include <cuda_runtime.h>
#include <cuda_fp16.h>
#include <cstdint>
#include <math.h>

// Qwen3.5 TopK Router — 3-pass FP16-split mma.sync(m16n8k16) + ldmatrix.
// Round-10 mainloop VERBATIM (best GEMM: producer at chunk tail, warp-parity
// kb stagger, JIT pass-ordered fragment loads) + warp-parallel redux-based
// softmax/top-8 epilogue (validated bit-exact in round 12).
// x' = x*1024, w' = w*64; hi = f16_rn(v), lo = f16_rn(v-hi);
// acc += Ah*Bh + Al*Bh + Ah*Bl; logits = acc/65536. Residual ~2^-22.
//
// Output (float32): [T*E logits][T*K weights][T*K indices-as-float]

#define D_DIM  2048
#define E_EXP  128
#define TOPK   8
#define BM     128
#define KC     32
#define NCH    (D_DIM / KC)       // 64
#define NT     512
#define LPAD   129

#define SX      1024.0f
#define SW      64.0f
#define RESCALE (1.0f / 65536.0f)

#define OFF_AH   0
#define OFF_AL   8192
#define OFF_BH   16384
#define OFF_BL   24576
#define STAGE_B  32768
#define SMEM_B   66560

#define MMA_F16(d, a0, a1, a2, a3, b0, b1)                                    \
    asm volatile(                                                             \
        "mma.sync.aligned.m16n8k16.row.col.f32.f16.f16.f32 "                  \
        "{%0,%1,%2,%3}, {%4,%5,%6,%7}, {%8,%9}, {%0,%1,%2,%3};"               \
        : "+f"((d)[0]), "+f"((d)[1]), "+f"((d)[2]), "+f"((d)[3])              \
        : "r"(a0), "r"(a1), "r"(a2), "r"(a3), "r"(b0), "r"(b1))

#define LDSM_X4(r, addr)                                                      \
    asm volatile(                                                             \
        "ldmatrix.sync.aligned.m8n8.x4.shared.b16 {%0,%1,%2,%3}, [%4];"       \
        : "=r"((r)[0]), "=r"((r)[1]), "=r"((r)[2]), "=r"((r)[3])              \
        : "r"(addr))

static __device__ __forceinline__ uint32_t smem_u32(const void* p) {
    uint32_t a;
    asm("{ .reg .u64 t; cvta.to.shared.u64 t, %1; cvt.u32.u64 %0, t; }"
        : "=r"(a) : "l"(p));
    return a;
}
static __device__ __forceinline__ void split2(float x0, float x1,
                                              uint32_t& hi, uint32_t& lo) {
    half2 h = __floats2half2_rn(x0, x1);
    float2 hf = __half22float2(h);
    half2 l = __floats2half2_rn(x0 - hf.x, x1 - hf.y);
    hi = *(uint32_t*)&h;
    lo = *(uint32_t*)&l;
}
static __device__ __forceinline__ void split4(float4 v, float s,
                                              uint2& hi, uint2& lo) {
    uint32_t h0, l0, h1, l1;
    split2(v.x * s, v.y * s, h0, l0);
    split2(v.z * s, v.w * s, h1, l1);
    hi = make_uint2(h0, h1);
    lo = make_uint2(l0, l1);
}
// orderable-uint transform for float max over possibly-negative values
static __device__ __forceinline__ uint32_t ford(float f) {
    uint32_t b = __float_as_uint(f);
    return b ^ (uint32_t)(((int32_t)b >> 31) | 0x80000000);
}
static __device__ __forceinline__ float finv(uint32_t u) {
    uint32_t m = (uint32_t)(((int32_t)(~u) >> 31) | 0x80000000);
    return __uint_as_float(u ^ m);
}

__global__ __launch_bounds__(NT, 1)
void router_mma(const float* __restrict__ X,
                const float* __restrict__ W,
                float* __restrict__ out, int T)
{
    extern __shared__ __align__(16) uint32_t smem[];

    const uint32_t sbase = smem_u32(smem);
    const int tid  = threadIdx.x;
    const int wid  = tid >> 5;
    const int lane = tid & 31;
    const int row0 = blockIdx.x * BM;

    // -------- producer mapping (64B rows, swizzle g ^ ((r>>1)&3)) --------
    const int psub = lane >> 3;
    const int pcol = (lane & 7) * 4;
    const int pg   = (lane & 7) >> 1;
    const int psb  = (lane & 1) * 8;
    const float* gA[2];
    const float* gB[2];
    uint32_t soff[2];
    #pragma unroll
    for (int q = 0; q < 2; q++) {
        const int r = 8 * wid + 4 * q + psub;
        gA[q] = X + (size_t)(row0 + r) * D_DIM + pcol;
        gB[q] = W + (size_t)r * D_DIM + pcol;
        soff[q] = (uint32_t)(r * 64 + ((pg ^ ((r >> 1) & 3)) << 4) + psb);
    }

    // -------- consumer mapping: warp grid 4(M) x 4(N), tile 32x32 --------
    const int g_  = lane >> 2;
    const int tg  = lane & 3;
    const int mrow0 = (wid & 3) * 32;
    const int ncol0 = (wid >> 2) * 32;
    const int kbo   = wid & 1;          // warp-parity kb stagger

    uint32_t offA[2][2], offB[2][2];
    {
        const int rA  = (lane & 7) + ((lane >> 3) & 1) * 8;
        const int gsA = lane >> 4;
        #pragma unroll
        for (int mt = 0; mt < 2; mt++) {
            const int row = mrow0 + mt * 16 + rA;
            const int sw  = (row >> 1) & 3;
            #pragma unroll
            for (int kb = 0; kb < 2; kb++)
                offA[mt][kb] = (uint32_t)(row * 64 + (((kb * 2 + gsA) ^ sw) << 4));
        }
        const int rB  = (lane & 7) + ((lane >> 4) << 3);
        const int gsB = (lane >> 3) & 1;
        #pragma unroll
        for (int p = 0; p < 2; p++) {
            const int row = ncol0 + p * 16 + rB;
            const int sw  = (row >> 1) & 3;
            #pragma unroll
            for (int kb = 0; kb < 2; kb++)
                offB[p][kb] = (uint32_t)(row * 64 + (((kb * 2 + gsB) ^ sw) << 4));
        }
    }

    float acc[2][4][4];
    #pragma unroll
    for (int mt = 0; mt < 2; mt++)
        #pragma unroll
        for (int nt = 0; nt < 4; nt++)
            #pragma unroll
            for (int i = 0; i < 4; i++) acc[mt][nt][i] = 0.0f;

    float4 ra[2], rb[2];

    // ---- prologue: chunk 0 -> stage 0 ----
    #pragma unroll
    for (int q = 0; q < 2; q++) {
        ra[q] = *(const float4*)gA[q];
        rb[q] = *(const float4*)gB[q];
    }
    {
        char* st = (char*)smem;
        #pragma unroll
        for (int q = 0; q < 2; q++) {
            uint2 hi, lo;
            split4(ra[q], SX, hi, lo);
            *(uint2*)(st + OFF_AH + soff[q]) = hi;
            *(uint2*)(st + OFF_AL + soff[q]) = lo;
            split4(rb[q], SW, hi, lo);
            *(uint2*)(st + OFF_BH + soff[q]) = hi;
            *(uint2*)(st + OFF_BL + soff[q]) = lo;
        }
    }
    __syncthreads();

    // ---- main loop (round 10 verbatim) ----
    for (int c = 0; c < NCH; ++c) {
        if (c + 1 < NCH) {
            const int ko = (c + 1) * KC;
            #pragma unroll
            for (int q = 0; q < 2; q++) {
                ra[q] = *(const float4*)(gA[q] + ko);
                rb[q] = *(const float4*)(gB[q] + ko);
            }
        }

        const uint32_t stg = sbase + (uint32_t)(c & 1) * STAGE_B;

        #pragma unroll
        for (int kbi = 0; kbi < 2; kbi++) {
            const int kb = kbi ^ kbo;       // stagger phase across warps
            uint32_t ah[2][4], al[2][4], bh[2][4], bl[2][4];

            // JIT loads: (ah,bh) -> hh; al -> lh; bl -> hl
            #pragma unroll
            for (int mt = 0; mt < 2; mt++)
                LDSM_X4(ah[mt], stg + OFF_AH + offA[mt][kb]);
            #pragma unroll
            for (int p = 0; p < 2; p++)
                LDSM_X4(bh[p], stg + OFF_BH + offB[p][kb]);

            #pragma unroll
            for (int mt = 0; mt < 2; mt++)
                #pragma unroll
                for (int nt = 0; nt < 4; nt++) {
                    const int p = nt >> 1, h = (nt & 1) * 2;
                    MMA_F16(acc[mt][nt], ah[mt][0], ah[mt][1], ah[mt][2], ah[mt][3],
                            bh[p][h], bh[p][h + 1]);
                }

            #pragma unroll
            for (int mt = 0; mt < 2; mt++)
                LDSM_X4(al[mt], stg + OFF_AL + offA[mt][kb]);

            #pragma unroll
            for (int mt = 0; mt < 2; mt++)
                #pragma unroll
                for (int nt = 0; nt < 4; nt++) {
                    const int p = nt >> 1, h = (nt & 1) * 2;
                    MMA_F16(acc[mt][nt], al[mt][0], al[mt][1], al[mt][2], al[mt][3],
                            bh[p][h], bh[p][h + 1]);
                }

            #pragma unroll
            for (int p = 0; p < 2; p++)
                LDSM_X4(bl[p], stg + OFF_BL + offB[p][kb]);

            #pragma unroll
            for (int mt = 0; mt < 2; mt++)
                #pragma unroll
                for (int nt = 0; nt < 4; nt++) {
                    const int p = nt >> 1, h = (nt & 1) * 2;
                    MMA_F16(acc[mt][nt], ah[mt][0], ah[mt][1], ah[mt][2], ah[mt][3],
                            bl[p][h], bl[p][h + 1]);
                }
        }

        if (c + 1 < NCH) {
            char* stn = (char*)smem + ((c + 1) & 1) * STAGE_B;
            #pragma unroll
            for (int q = 0; q < 2; q++) {
                uint2 hi, lo;
                split4(ra[q], SX, hi, lo);
                *(uint2*)(stn + OFF_AH + soff[q]) = hi;
                *(uint2*)(stn + OFF_AL + soff[q]) = lo;
                split4(rb[q], SW, hi, lo);
                *(uint2*)(stn + OFF_BH + soff[q]) = hi;
                *(uint2*)(stn + OFF_BL + soff[q]) = lo;
            }
        }
        __syncthreads();
    }

    // ---- epilogue: rescale accum -> smem logits tile ----
    float* Ls = (float*)smem;   // [BM][LPAD]
    #pragma unroll
    for (int mt = 0; mt < 2; mt++) {
        #pragma unroll
        for (int nt = 0; nt < 4; nt++) {
            const int r_ = mrow0 + mt * 16 + g_;
            const int c_ = ncol0 + nt * 8 + tg * 2;
            Ls[r_ * LPAD + c_]           = acc[mt][nt][0] * RESCALE;
            Ls[r_ * LPAD + c_ + 1]       = acc[mt][nt][1] * RESCALE;
            Ls[(r_ + 8) * LPAD + c_]     = acc[mt][nt][2] * RESCALE;
            Ls[(r_ + 8) * LPAD + c_ + 1] = acc[mt][nt][3] * RESCALE;
        }
    }
    __syncthreads();

    // ---- warp-parallel softmax + top-8: warp w -> tokens 8w..8w+7 ----
    const size_t wbase = (size_t)T * E_EXP;
    const size_t xbase = wbase + (size_t)T * TOPK;
    #pragma unroll 1
    for (int j = 0; j < 8; j++) {
        const int t = wid * 8 + j;
        const float* lr = Ls + t * LPAD + lane;
        float v0 = lr[0], v1 = lr[32], v2 = lr[64], v3 = lr[96];

        // warp max (redux on ordered uints)
        float mx = fmaxf(fmaxf(v0, v1), fmaxf(v2, v3));
        mx = finv(__reduce_max_sync(0xFFFFFFFFu, ford(mx)));

        float e0 = __expf(v0 - mx), e1 = __expf(v1 - mx);
        float e2 = __expf(v2 - mx), e3 = __expf(v3 - mx);
        float s = (e0 + e1) + (e2 + e3);
        #pragma unroll
        for (int o = 16; o > 0; o >>= 1) s += __shfl_xor_sync(0xFFFFFFFFu, s, o);
        const float rs = 1.0f / s;

        // probabilities (coalesced 128B stores per group)
        float* po = out + (size_t)(row0 + t) * E_EXP + lane;
        po[0]  = e0 * rs;
        po[32] = e1 * rs;
        po[64] = e2 * rs;
        po[96] = e3 * rs;

        // top-8 on e (positive floats order as uints); lowest index on ties
        float wv = 0.0f; int wi = 0; float s8 = 0.0f;
        #pragma unroll
        for (int k = 0; k < TOPK; k++) {
            float bv = e0; int bq = 0;
            if (e1 > bv) { bv = e1; bq = 1; }
            if (e2 > bv) { bv = e2; bq = 2; }
            if (e3 > bv) { bv = e3; bq = 3; }
            const uint32_t kbits = __float_as_uint(bv);
            const uint32_t wk = __reduce_max_sync(0xFFFFFFFFu, kbits);
            uint32_t cand = (kbits == wk) ? (uint32_t)(lane + 32 * bq)
                                          : 0xFFFFFFFFu;
            const uint32_t idx = __reduce_min_sync(0xFFFFFFFFu, cand);
            const float bval = __uint_as_float(wk);
            s8 += bval;
            if (lane == k) { wv = bval; wi = (int)idx; }
            if ((int)(idx & 31u) == lane) {
                const int q = (int)(idx >> 5);
                e0 = (q == 0) ? -1.0f : e0;
                e1 = (q == 1) ? -1.0f : e1;
                e2 = (q == 2) ? -1.0f : e2;
                e3 = (q == 3) ? -1.0f : e3;
            }
        }
        if (lane < TOPK) {
            const float rs8 = 1.0f / s8;
            out[wbase + (size_t)(row0 + t) * TOPK + lane] = wv * rs8;
            out[xbase + (size_t)(row0 + t) * TOPK + lane] = (float)wi;
        }
    }
}

extern "C" void kernel_launch(void* const* d_in, const int* in_sizes, int n_in,
                              void* d_out, int out_size)
{
    const float* X = (const float*)d_in[0];   // hidden_states [T, 2048]
    const float* W = (const float*)d_in[1];   // weight        [128, 2048]
    float* out = (float*)d_out;

    const int T = in_sizes[0] / D_DIM;        // 16384
    static int configured = -1;
    if (configured < 0) {
        cudaFuncSetAttribute(router_mma,
                             cudaFuncAttributeMaxDynamicSharedMemorySize, SMEM_B);
        configured = 1;
    }
    router_mma<<<T / BM, NT, SMEM_B>>>(X, W, out, T);
}

// round 14
// speedup vs baseline: 1.4838x; 1.0451x over previous
#include <cuda_runtime.h>
#include <cuda_fp16.h>
#include <cstdint>
#include <math.h>

// Qwen3.5 TopK Router — 3-pass FP16-split mma.sync(m16n8k16) + ldmatrix.
// Warp-level split-K: warp grid 2(M) x 4(N) x 2(K), warp tile 64x32 ->
// LDSM bytes per MAC x0.75+B-amortized (chip smem 196->98 KB/chunk);
// half-K partials summed in smem epilogue. Redux softmax/top-8 epilogue.
// x' = x*1024, w' = w*64; hi = f16_rn(v), lo = f16_rn(v-hi);
// acc += Ah*Bh + Al*Bh + Ah*Bl; logits = acc/65536. Residual ~2^-22.
//
// Output (float32): [T*E logits][T*K weights][T*K indices-as-float]

#define D_DIM  2048
#define E_EXP  128
#define TOPK   8
#define BM     128
#define KC     32
#define NCH    (D_DIM / KC)       // 64
#define NT     512
#define LPAD   129

#define SX      1024.0f
#define SW      64.0f
#define RESCALE (1.0f / 65536.0f)

#define OFF_AH   0
#define OFF_AL   8192
#define OFF_BH   16384
#define OFF_BL   24576
#define STAGE_B  32768
#define SMEM_B   66560

#define MMA_F16(d, a0, a1, a2, a3, b0, b1)                                    \
    asm volatile(                                                             \
        "mma.sync.aligned.m16n8k16.row.col.f32.f16.f16.f32 "                  \
        "{%0,%1,%2,%3}, {%4,%5,%6,%7}, {%8,%9}, {%0,%1,%2,%3};"               \
        : "+f"((d)[0]), "+f"((d)[1]), "+f"((d)[2]), "+f"((d)[3])              \
        : "r"(a0), "r"(a1), "r"(a2), "r"(a3), "r"(b0), "r"(b1))

#define LDSM_X4(r, addr)                                                      \
    asm volatile(                                                             \
        "ldmatrix.sync.aligned.m8n8.x4.shared.b16 {%0,%1,%2,%3}, [%4];"       \
        : "=r"((r)[0]), "=r"((r)[1]), "=r"((r)[2]), "=r"((r)[3])              \
        : "r"(addr))

static __device__ __forceinline__ uint32_t smem_u32(const void* p) {
    uint32_t a;
    asm("{ .reg .u64 t; cvta.to.shared.u64 t, %1; cvt.u32.u64 %0, t; }"
        : "=r"(a) : "l"(p));
    return a;
}
static __device__ __forceinline__ void split2(float x0, float x1,
                                              uint32_t& hi, uint32_t& lo) {
    half2 h = __floats2half2_rn(x0, x1);
    float2 hf = __half22float2(h);
    half2 l = __floats2half2_rn(x0 - hf.x, x1 - hf.y);
    hi = *(uint32_t*)&h;
    lo = *(uint32_t*)&l;
}
static __device__ __forceinline__ void split4(float4 v, float s,
                                              uint2& hi, uint2& lo) {
    uint32_t h0, l0, h1, l1;
    split2(v.x * s, v.y * s, h0, l0);
    split2(v.z * s, v.w * s, h1, l1);
    hi = make_uint2(h0, h1);
    lo = make_uint2(l0, l1);
}
static __device__ __forceinline__ uint32_t ford(float f) {
    uint32_t b = __float_as_uint(f);
    return b ^ (uint32_t)(((int32_t)b >> 31) | 0x80000000);
}
static __device__ __forceinline__ float finv(uint32_t u) {
    uint32_t m = (uint32_t)(((int32_t)(~u) >> 31) | 0x80000000);
    return __uint_as_float(u ^ m);
}

__global__ __launch_bounds__(NT, 1)
void router_mma(const float* __restrict__ X,
                const float* __restrict__ W,
                float* __restrict__ out, int T)
{
    extern __shared__ __align__(16) uint32_t smem[];

    const uint32_t sbase = smem_u32(smem);
    const int tid  = threadIdx.x;
    const int wid  = tid >> 5;
    const int lane = tid & 31;
    const int row0 = blockIdx.x * BM;

    // -------- producer mapping (64B rows, swizzle g ^ ((r>>1)&3)) --------
    const int psub = lane >> 3;
    const int pcol = (lane & 7) * 4;
    const int pg   = (lane & 7) >> 1;
    const int psb  = (lane & 1) * 8;
    const float* gA[2];
    const float* gB[2];
    uint32_t soff[2];
    #pragma unroll
    for (int q = 0; q < 2; q++) {
        const int r = 8 * wid + 4 * q + psub;
        gA[q] = X + (size_t)(row0 + r) * D_DIM + pcol;
        gB[q] = W + (size_t)r * D_DIM + pcol;
        soff[q] = (uint32_t)(r * 64 + ((pg ^ ((r >> 1) & 3)) << 4) + psb);
    }

    // -------- consumer: warp grid 2(M) x 4(N) x 2(K); tile 64x32 --------
    const int kslice = wid & 1;          // k16-block owned by this warp
    const int wm     = (wid >> 1) & 1;
    const int wn     = wid >> 2;
    const int g_  = lane >> 2;
    const int tg  = lane & 3;
    const int mrow0 = wm * 64;
    const int ncol0 = wn * 32;

    uint32_t offA[4], offB[2];
    {
        const int rA  = (lane & 7) + ((lane >> 3) & 1) * 8;
        const int gsA = lane >> 4;
        #pragma unroll
        for (int mt = 0; mt < 4; mt++) {
            const int row = mrow0 + mt * 16 + rA;
            const int sw  = (row >> 1) & 3;
            offA[mt] = (uint32_t)(row * 64 + (((kslice * 2 + gsA) ^ sw) << 4));
        }
        const int rB  = (lane & 7) + ((lane >> 4) << 3);
        const int gsB = (lane >> 3) & 1;
        #pragma unroll
        for (int p = 0; p < 2; p++) {
            const int row = ncol0 + p * 16 + rB;
            const int sw  = (row >> 1) & 3;
            offB[p] = (uint32_t)(row * 64 + (((kslice * 2 + gsB) ^ sw) << 4));
        }
    }

    float acc[4][4][4];
    #pragma unroll
    for (int mt = 0; mt < 4; mt++)
        #pragma unroll
        for (int nt = 0; nt < 4; nt++)
            #pragma unroll
            for (int i = 0; i < 4; i++) acc[mt][nt][i] = 0.0f;

    float4 ra[2], rb[2];

    // ---- prologue: chunk 0 -> stage 0 ----
    #pragma unroll
    for (int q = 0; q < 2; q++) {
        ra[q] = *(const float4*)gA[q];
        rb[q] = *(const float4*)gB[q];
    }
    {
        char* st = (char*)smem;
        #pragma unroll
        for (int q = 0; q < 2; q++) {
            uint2 hi, lo;
            split4(ra[q], SX, hi, lo);
            *(uint2*)(st + OFF_AH + soff[q]) = hi;
            *(uint2*)(st + OFF_AL + soff[q]) = lo;
            split4(rb[q], SW, hi, lo);
            *(uint2*)(st + OFF_BH + soff[q]) = hi;
            *(uint2*)(st + OFF_BL + soff[q]) = lo;
        }
    }
    __syncthreads();

    // ---- main loop ----
    for (int c = 0; c < NCH; ++c) {
        if (c + 1 < NCH) {
            const int ko = (c + 1) * KC;
            #pragma unroll
            for (int q = 0; q < 2; q++) {
                ra[q] = *(const float4*)(gA[q] + ko);
                rb[q] = *(const float4*)(gB[q] + ko);
            }
        }

        const uint32_t stg = sbase + (uint32_t)(c & 1) * STAGE_B;

        // B fragments once per chunk (this warp's kslice only)
        uint32_t bh[2][4], bl[2][4];
        #pragma unroll
        for (int p = 0; p < 2; p++) {
            LDSM_X4(bh[p], stg + OFF_BH + offB[p]);
            LDSM_X4(bl[p], stg + OFF_BL + offB[p]);
        }

        // per-mt JIT A fragments; 12 MMAs per mt (hh, lh, hl)
        #pragma unroll
        for (int mt = 0; mt < 4; mt++) {
            uint32_t ah[4], al[4];
            LDSM_X4(ah, stg + OFF_AH + offA[mt]);
            LDSM_X4(al, stg + OFF_AL + offA[mt]);

            #pragma unroll
            for (int nt = 0; nt < 4; nt++) {
                const int p = nt >> 1, h = (nt & 1) * 2;
                MMA_F16(acc[mt][nt], ah[0], ah[1], ah[2], ah[3],
                        bh[p][h], bh[p][h + 1]);
            }
            #pragma unroll
            for (int nt = 0; nt < 4; nt++) {
                const int p = nt >> 1, h = (nt & 1) * 2;
                MMA_F16(acc[mt][nt], al[0], al[1], al[2], al[3],
                        bh[p][h], bh[p][h + 1]);
            }
            #pragma unroll
            for (int nt = 0; nt < 4; nt++) {
                const int p = nt >> 1, h = (nt & 1) * 2;
                MMA_F16(acc[mt][nt], ah[0], ah[1], ah[2], ah[3],
                        bl[p][h], bl[p][h + 1]);
            }
        }

        if (c + 1 < NCH) {
            char* stn = (char*)smem + ((c + 1) & 1) * STAGE_B;
            #pragma unroll
            for (int q = 0; q < 2; q++) {
                uint2 hi, lo;
                split4(ra[q], SX, hi, lo);
                *(uint2*)(stn + OFF_AH + soff[q]) = hi;
                *(uint2*)(stn + OFF_AL + soff[q]) = lo;
                split4(rb[q], SW, hi, lo);
                *(uint2*)(stn + OFF_BH + soff[q]) = hi;
                *(uint2*)(stn + OFF_BL + soff[q]) = lo;
            }
        }
        __syncthreads();
    }

    // ---- epilogue: half-K merge in smem logits tile ----
    float* Ls = (float*)smem;   // [BM][LPAD]
    if (kslice == 0) {
        #pragma unroll
        for (int mt = 0; mt < 4; mt++)
            #pragma unroll
            for (int nt = 0; nt < 4; nt++) {
                const int r_ = mrow0 + mt * 16 + g_;
                const int c_ = ncol0 + nt * 8 + tg * 2;
                Ls[r_ * LPAD + c_]           = acc[mt][nt][0] * RESCALE;
                Ls[r_ * LPAD + c_ + 1]       = acc[mt][nt][1] * RESCALE;
                Ls[(r_ + 8) * LPAD + c_]     = acc[mt][nt][2] * RESCALE;
                Ls[(r_ + 8) * LPAD + c_ + 1] = acc[mt][nt][3] * RESCALE;
            }
    }
    __syncthreads();
    if (kslice == 1) {
        #pragma unroll
        for (int mt = 0; mt < 4; mt++)
            #pragma unroll
            for (int nt = 0; nt < 4; nt++) {
                const int r_ = mrow0 + mt * 16 + g_;
                const int c_ = ncol0 + nt * 8 + tg * 2;
                Ls[r_ * LPAD + c_]           += acc[mt][nt][0] * RESCALE;
                Ls[r_ * LPAD + c_ + 1]       += acc[mt][nt][1] * RESCALE;
                Ls[(r_ + 8) * LPAD + c_]     += acc[mt][nt][2] * RESCALE;
                Ls[(r_ + 8) * LPAD + c_ + 1] += acc[mt][nt][3] * RESCALE;
            }
    }
    __syncthreads();

    // ---- warp-parallel softmax + top-8: warp w -> tokens 8w..8w+7 ----
    const size_t wbase = (size_t)T * E_EXP;
    const size_t xbase = wbase + (size_t)T * TOPK;
    #pragma unroll 1
    for (int j = 0; j < 8; j++) {
        const int t = wid * 8 + j;
        const float* lr = Ls + t * LPAD + lane;
        float v0 = lr[0], v1 = lr[32], v2 = lr[64], v3 = lr[96];

        float mx = fmaxf(fmaxf(v0, v1), fmaxf(v2, v3));
        mx = finv(__reduce_max_sync(0xFFFFFFFFu, ford(mx)));

        float e0 = __expf(v0 - mx), e1 = __expf(v1 - mx);
        float e2 = __expf(v2 - mx), e3 = __expf(v3 - mx);
        float s = (e0 + e1) + (e2 + e3);
        #pragma unroll
        for (int o = 16; o > 0; o >>= 1) s += __shfl_xor_sync(0xFFFFFFFFu, s, o);
        const float rs = 1.0f / s;

        float* po = out + (size_t)(row0 + t) * E_EXP + lane;
        po[0]  = e0 * rs;
        po[32] = e1 * rs;
        po[64] = e2 * rs;
        po[96] = e3 * rs;

        float wv = 0.0f; int wi = 0; float s8 = 0.0f;
        #pragma unroll
        for (int k = 0; k < TOPK; k++) {
            float bv = e0; int bq = 0;
            if (e1 > bv) { bv = e1; bq = 1; }
            if (e2 > bv) { bv = e2; bq = 2; }
            if (e3 > bv) { bv = e3; bq = 3; }
            const uint32_t kbits = __float_as_uint(bv);
            const uint32_t wk = __reduce_max_sync(0xFFFFFFFFu, kbits);
            uint32_t cand = (kbits == wk) ? (uint32_t)(lane + 32 * bq)
                                          : 0xFFFFFFFFu;
            const uint32_t idx = __reduce_min_sync(0xFFFFFFFFu, cand);
            const float bval = __uint_as_float(wk);
            s8 += bval;
            if (lane == k) { wv = bval; wi = (int)idx; }
            if ((int)(idx & 31u) == lane) {
                const int q = (int)(idx >> 5);
                e0 = (q == 0) ? -1.0f : e0;
                e1 = (q == 1) ? -1.0f : e1;
                e2 = (q == 2) ? -1.0f : e2;
                e3 = (q == 3) ? -1.0f : e3;
            }
        }
        if (lane < TOPK) {
            const float rs8 = 1.0f / s8;
            out[wbase + (size_t)(row0 + t) * TOPK + lane] = wv * rs8;
            out[xbase + (size_t)(row0 + t) * TOPK + lane] = (float)wi;
        }
    }
}

extern "C" void kernel_launch(void* const* d_in, const int* in_sizes, int n_in,
                              void* d_out, int out_size)
{
    const float* X = (const float*)d_in[0];   // hidden_states [T, 2048]
    const float* W = (const float*)d_in[1];   // weight        [128, 2048]
    float* out = (float*)d_out;

    const int T = in_sizes[0] / D_DIM;        // 16384
    static int configured = -1;
    if (configured < 0) {
        cudaFuncSetAttribute(router_mma,
                             cudaFuncAttributeMaxDynamicSharedMemorySize, SMEM_B);
        configured = 1;
    }
    router_mma<<<T / BM, NT, SMEM_B>>>(X, W, out, T);
}